// round 6
// baseline (speedup 1.0000x reference)
#include <cuda_runtime.h>
#include <float.h>
#include <math.h>

#define BATCH 2
#define NPTS 8192
#define KNN 16
#define THREADS 128
#define NQ_TOTAL (2 * BATCH * NPTS)       // 32768 query slots
#define QPT 2                             // queries per thread in the scan
#define QBLK (THREADS * QPT)              // 256 queries per scan block
#define NQBLOCKS (NQ_TOTAL / QBLK)        // 128 query blocks (scan)
#define SELBLOCKS (NQ_TOTAL / THREADS)    // 256 blocks (tau / select)
#define SPLITS 4
#define SPLIT_PTS (NPTS / SPLITS)         // 2048 ref points per scan block
#define NSCAN (SPLITS * NQBLOCKS)         // 512 scan blocks
#define CAPH 192                          // candidate capacity / query / split (E~64, +16 sigma)
#define SUB 512                           // threshold-pass subset size

__device__ float g_partials[SELBLOCKS];
__device__ float g_tau[NQ_TOTAL];
__device__ int   g_cnt[SPLITS * NQ_TOTAL];
// candidate scratch, column-major per split: g_scratch[split][slot][gq]
__device__ float g_scratch[(size_t)SPLITS * CAPH * NQ_TOTAL];   // ~100 MB static

__device__ __forceinline__ void load_query(const float* __restrict__ src,
                                           const float* __restrict__ tgt,
                                           const float* __restrict__ flow,
                                           int gq, float& qx, float& qy, float& qz) {
    const int set = gq / NPTS;            // 0..3 : (batch, direction)
    const int b   = set >> 1;
    const int dir = set & 1;
    const int qi  = gq - set * NPTS;
    const float* sb = src  + (size_t)b * NPTS * 3;
    const float* tb = tgt  + (size_t)b * NPTS * 3;
    const float* fb = flow + (size_t)b * NPTS * 3;
    if (dir == 0) {
        qx = sb[qi * 3 + 0] + fb[qi * 3 + 0];
        qy = sb[qi * 3 + 1] + fb[qi * 3 + 1];
        qz = sb[qi * 3 + 2] + fb[qi * 3 + 2];
    } else {
        qx = tb[qi * 3 + 0];
        qy = tb[qi * 3 + 1];
        qz = tb[qi * 3 + 2];
    }
}

// stage ref points [g0, g0+cnt) for query-set `set` as (x,y,z,|r|^2/2)
__device__ __forceinline__ void stage_refs(const float* __restrict__ src,
                                           const float* __restrict__ tgt,
                                           const float* __restrict__ flow,
                                           int set, int g0, int cnt,
                                           float4* __restrict__ sm, int tid) {
    const int b   = set >> 1;
    const int dir = set & 1;
    const float* sb = src  + (size_t)b * NPTS * 3;
    const float* tb = tgt  + (size_t)b * NPTS * 3;
    const float* fb = flow + (size_t)b * NPTS * 3;
    for (int p = tid; p < cnt; p += THREADS) {
        const int g = g0 + p;
        float x, y, z;
        if (dir == 0) {          // query = pred, ref = target
            x = tb[g * 3 + 0];
            y = tb[g * 3 + 1];
            z = tb[g * 3 + 2];
        } else {                 // query = target, ref = pred = src + flow
            x = sb[g * 3 + 0] + fb[g * 3 + 0];
            y = sb[g * 3 + 1] + fb[g * 3 + 1];
            z = sb[g * 3 + 2] + fb[g * 3 + 2];
        }
        sm[p] = make_float4(x, y, z, 0.5f * (x * x + (y * y + z * z)));
    }
}

// exact 16th-smallest score over a 512-point subset -> g_tau
__global__ void __launch_bounds__(THREADS)
tau_kernel(const float* __restrict__ src,
           const float* __restrict__ tgt,
           const float* __restrict__ flow) {
    __shared__ float4 sub[SUB];
    const int tid = threadIdx.x;
    const int gq  = blockIdx.x * THREADS + tid;
    const int set = gq / NPTS;

    stage_refs(src, tgt, flow, set, 0, SUB, sub, tid);

    float qx, qy, qz;
    load_query(src, tgt, flow, gq, qx, qy, qz);
    __syncthreads();

    float best[KNN];
#pragma unroll
    for (int i = 0; i < KNN; i++) best[i] = FLT_MAX;

#pragma unroll 4
    for (int j = 0; j < SUB; j++) {
        const float4 r = sub[j];
        float sc = fmaf(-qx, r.x, r.w);
        sc = fmaf(-qy, r.y, sc);
        sc = fmaf(-qz, r.z, sc);
        const bool ins = sc < best[0];
        if (__any_sync(0xffffffffu, ins)) {
            best[0] = ins ? sc : best[0];
#pragma unroll
            for (int i = 0; i < KNN - 1; i++) {
                const float a = best[i], c = best[i + 1];
                best[i]     = fmaxf(a, c);
                best[i + 1] = fminf(a, c);
            }
        }
    }
    g_tau[gq] = best[0];
}

// stateless filter, 2 queries per thread: one LDS.128 feeds both queries
__global__ void __launch_bounds__(THREADS)
scan_kernel(const float* __restrict__ src,
            const float* __restrict__ tgt,
            const float* __restrict__ flow) {
    __shared__ float4 spts[SPLIT_PTS];   // 32 KB

    const int tid   = threadIdx.x;
    const int split = blockIdx.x >> 7;            // 0..3
    const int qblk  = blockIdx.x & 127;           // 0..127
    const int gq0   = qblk * QBLK + tid;          // first query
    const int gq1   = gq0 + THREADS;              // second query (same set)
    const int set   = gq0 / NPTS;

    stage_refs(src, tgt, flow, set, split * SPLIT_PTS, SPLIT_PTS, spts, tid);

    float q0x, q0y, q0z, q1x, q1y, q1z;
    load_query(src, tgt, flow, gq0, q0x, q0y, q0z);
    load_query(src, tgt, flow, gq1, q1x, q1y, q1z);
    float tau0 = g_tau[gq0];
    float tau1 = g_tau[gq1];
    __syncthreads();

    float* const w0base  = g_scratch + (size_t)split * CAPH * NQ_TOTAL + gq0;
    float* const w1base  = g_scratch + (size_t)split * CAPH * NQ_TOTAL + gq1;
    float*       wp0     = w0base;
    float*       wp1     = w1base;
    float* const w0guard = w0base + (size_t)(CAPH - 8) * NQ_TOTAL;
    float* const w1guard = w1base + (size_t)(CAPH - 8) * NQ_TOTAL;

    for (int j0 = 0; j0 < SPLIT_PTS; j0 += 8) {
        // overflow belts (P ~ +16 sigma, never fire)
        if (wp0 >= w0guard) tau0 = -FLT_MAX;
        if (wp1 >= w1guard) tau1 = -FLT_MAX;
#pragma unroll
        for (int jj = 0; jj < 8; jj++) {
            const float4 r = spts[j0 + jj];
            float s0 = fmaf(-q0x, r.x, r.w);
            s0 = fmaf(-q0y, r.y, s0);
            s0 = fmaf(-q0z, r.z, s0);
            float s1 = fmaf(-q1x, r.x, r.w);
            s1 = fmaf(-q1y, r.y, s1);
            s1 = fmaf(-q1z, r.z, s1);
            if (s0 <= tau0) { *wp0 = s0; wp0 += NQ_TOTAL; }
            if (s1 <= tau1) { *wp1 = s1; wp1 += NQ_TOTAL; }
        }
    }
    g_cnt[split * NQ_TOTAL + gq0] = (int)((wp0 - w0base) / NQ_TOTAL);
    g_cnt[split * NQ_TOTAL + gq1] = (int)((wp1 - w1base) / NQ_TOTAL);
}

__global__ void __launch_bounds__(THREADS)
select_kernel(const float* __restrict__ src,
              const float* __restrict__ tgt,
              const float* __restrict__ flow) {
    const int tid = threadIdx.x;
    const int gq  = blockIdx.x * THREADS + tid;

    float qx, qy, qz;
    load_query(src, tgt, flow, gq, qx, qy, qz);
    const float q2 = qx * qx + qy * qy + qz * qz;

    float best[KNN];
#pragma unroll
    for (int i = 0; i < KNN; i++) best[i] = FLT_MAX;

#pragma unroll
    for (int split = 0; split < SPLITS; split++) {
        const float* const rbase = g_scratch + (size_t)split * CAPH * NQ_TOTAL + gq;
        const int cnt  = g_cnt[split * NQ_TOTAL + gq];
        const int mcnt = __reduce_max_sync(0xffffffffu, cnt);
        for (int i = 0; i < mcnt; i++) {
            const float v = rbase[(size_t)i * NQ_TOTAL];   // coalesced LDG
            const bool ins = (i < cnt) && (v < best[0]);
            if (__any_sync(0xffffffffu, ins)) {
                best[0] = ins ? v : best[0];
#pragma unroll
                for (int k = 0; k < KNN - 1; k++) {
                    const float a = best[k], c = best[k + 1];
                    best[k]     = fmaxf(a, c);
                    best[k + 1] = fminf(a, c);
                }
            }
        }
    }

    // sum of the 16 euclidean distances: d = sqrt(2*score + |q|^2)
    float s = 0.f;
#pragma unroll
    for (int i = 0; i < KNN; i++) {
        const float d2 = fmaf(2.f, best[i], q2);
        s += sqrtf(fmaxf(d2, 0.f));
    }

    __shared__ float warpsum[THREADS / 32];
#pragma unroll
    for (int o = 16; o > 0; o >>= 1) s += __shfl_down_sync(0xffffffffu, s, o);
    if ((tid & 31) == 0) warpsum[tid >> 5] = s;
    __syncthreads();
    if (tid == 0) {
        float tot = 0.f;
#pragma unroll
        for (int w = 0; w < THREADS / 32; w++) tot += warpsum[w];
        g_partials[blockIdx.x] = tot;
    }
}

__global__ void __launch_bounds__(SELBLOCKS)
finalize_kernel(float* __restrict__ out) {
    __shared__ float sh[SELBLOCKS];
    const int tid = threadIdx.x;
    sh[tid] = g_partials[tid];
    __syncthreads();
#pragma unroll
    for (int s = SELBLOCKS / 2; s > 0; s >>= 1) {
        if (tid < s) sh[tid] += sh[tid + s];
        __syncthreads();
    }
    if (tid == 0) {
        out[0] = sh[0] * (1.0f / (float)(KNN * BATCH * NPTS));
    }
}

extern "C" void kernel_launch(void* const* d_in, const int* in_sizes, int n_in,
                              void* d_out, int out_size) {
    const float* src  = (const float*)d_in[0];   // pc_source [B, N, 3]
    const float* tgt  = (const float*)d_in[1];   // pc_target [B, M, 3]
    const float* flow = (const float*)d_in[2];   // pred_flow [B, N, 3]
    float* out = (float*)d_out;

    tau_kernel<<<SELBLOCKS, THREADS>>>(src, tgt, flow);
    scan_kernel<<<NSCAN, THREADS>>>(src, tgt, flow);
    select_kernel<<<SELBLOCKS, THREADS>>>(src, tgt, flow);
    finalize_kernel<<<1, SELBLOCKS>>>(out);
}

// round 7
// speedup vs baseline: 1.2478x; 1.2478x over previous
#include <cuda_runtime.h>
#include <float.h>
#include <math.h>

#define BATCH 2
#define NPTS 8192
#define KNN 16
#define TILE 2048                       // 2048 * 16B = 32 KB static smem
#define THREADS 128
#define NBLOCKS (2 * BATCH * NPTS / THREADS)   // 256
#define NQ_TOTAL (2 * BATCH * NPTS)            // 32768
#define CAP 1024                        // candidate capacity per query
#define SUB 512                         // threshold-pass subset size

__device__ float g_partials[NBLOCKS];
__device__ float g_scratch[(size_t)CAP * NQ_TOTAL];   // 134 MB static scratch

// branch-free candidate emit: predicated store + predicated pointer bump.
// NO BSSY/BSYNC — ptxas keeps @p forms from explicit PTX predication.
__device__ __forceinline__ float* cond_store(float* wp, float sc, float tau) {
    asm volatile(
        "{\n\t"
        ".reg .pred p;\n\t"
        "setp.le.f32 p, %1, %2;\n\t"
        "@p st.global.f32 [%0], %1;\n\t"
        "@p add.u64 %0, %0, %3;\n\t"
        "}"
        : "+l"(wp)
        : "f"(sc), "f"(tau), "n"((unsigned long long)(NQ_TOTAL * sizeof(float)))
        : "memory");
    return wp;
}

// unconditional sorted-descending top-K insert (pure FMNMX, straight-line)
__device__ __forceinline__ void bubble_insert(float* best, float sc) {
    best[0] = fminf(best[0], sc);   // replace current worst iff sc is smaller
#pragma unroll
    for (int i = 0; i < KNN - 1; i++) {
        const float a = best[i], c = best[i + 1];
        best[i]     = fmaxf(a, c);
        best[i + 1] = fminf(a, c);
    }
}

__global__ void __launch_bounds__(THREADS)
chamfer_knn_kernel(const float* __restrict__ src,
                   const float* __restrict__ tgt,
                   const float* __restrict__ flow) {
    __shared__ float4 spts[TILE];

    const int tid = threadIdx.x;
    const int gq  = blockIdx.x * THREADS + tid;       // global query slot
    const int blocks_per_set = NPTS / THREADS;        // 64
    const int set = blockIdx.x / blocks_per_set;      // (batch, direction)
    const int b   = set >> 1;
    const int dir = set & 1;                          // 0: pred->target, 1: target->pred
    const int qi  = (blockIdx.x % blocks_per_set) * THREADS + tid;

    const float* __restrict__ srcb = src  + (size_t)b * NPTS * 3;
    const float* __restrict__ tgtb = tgt  + (size_t)b * NPTS * 3;
    const float* __restrict__ flob = flow + (size_t)b * NPTS * 3;

    float qx, qy, qz;
    if (dir == 0) {
        qx = srcb[qi * 3 + 0] + flob[qi * 3 + 0];
        qy = srcb[qi * 3 + 1] + flob[qi * 3 + 1];
        qz = srcb[qi * 3 + 2] + flob[qi * 3 + 2];
    } else {
        qx = tgtb[qi * 3 + 0];
        qy = tgtb[qi * 3 + 1];
        qz = tgtb[qi * 3 + 2];
    }
    const float q2 = qx * qx + qy * qy + qz * qz;

    float best[KNN];
#pragma unroll
    for (int i = 0; i < KNN; i++) best[i] = FLT_MAX;

    float tau = FLT_MAX;
    float* const wbase  = g_scratch + gq;
    float*       wp     = wbase;
    float* const wguard = wbase + (size_t)(CAP - 8) * NQ_TOTAL;

    for (int t0 = 0; t0 < NPTS; t0 += TILE) {
        // stage ref tile as (x, y, z, |r|^2/2)
        for (int p = tid; p < TILE; p += THREADS) {
            const int g = t0 + p;
            float x, y, z;
            if (dir == 0) {
                x = tgtb[g * 3 + 0];
                y = tgtb[g * 3 + 1];
                z = tgtb[g * 3 + 2];
            } else {
                x = srcb[g * 3 + 0] + flob[g * 3 + 0];
                y = srcb[g * 3 + 1] + flob[g * 3 + 1];
                z = srcb[g * 3 + 2] + flob[g * 3 + 2];
            }
            const float w = 0.5f * (x * x + (y * y + z * z));
            spts[p] = make_float4(x, y, z, w);
        }
        __syncthreads();

        if (t0 == 0) {
            // threshold pass: exact top-16 over the first SUB points,
            // fully unconditional (no vote, no branch)
#pragma unroll 4
            for (int j = 0; j < SUB; j++) {
                const float4 r = spts[j];
                float sc = fmaf(-qx, r.x, r.w);
                sc = fmaf(-qy, r.y, sc);
                sc = fmaf(-qz, r.z, sc);
                bubble_insert(best, sc);
            }
            tau = best[0];   // upper bound on true 16th-smallest score
        }

        // streaming collect: branch-free predicated stores, no top-k state
        for (int j0 = 0; j0 < TILE; j0 += 8) {
            tau = (wp >= wguard) ? -FLT_MAX : tau;   // SEL, never fires statistically
#pragma unroll
            for (int jj = 0; jj < 8; jj++) {
                const float4 r = spts[j0 + jj];
                float sc = fmaf(-qx, r.x, r.w);
                sc = fmaf(-qy, r.y, sc);
                sc = fmaf(-qz, r.z, sc);
                wp = cond_store(wp, sc, tau);
            }
        }
        __syncthreads();
    }

    // final exact selection over collected candidates (superset of true top-16)
    const int cnt  = (int)((wp - wbase) / NQ_TOTAL);
    const int mcnt = __reduce_max_sync(0xffffffffu, cnt);
#pragma unroll
    for (int i = 0; i < KNN; i++) best[i] = FLT_MAX;   // reinit: avoid double count

    for (int i = 0; i < mcnt; i++) {
        float v = wbase[(size_t)i * NQ_TOTAL];          // coalesced LDG
        v = (i < cnt) ? v : FLT_MAX;                    // SEL, branch-free
        bubble_insert(best, v);
    }

    // sum of the 16 euclidean distances: d = sqrt(2*score + |q|^2)
    float s = 0.f;
#pragma unroll
    for (int i = 0; i < KNN; i++) {
        const float d2 = fmaf(2.f, best[i], q2);
        s += sqrtf(fmaxf(d2, 0.f));
    }

    // deterministic block reduction
    __shared__ float warpsum[THREADS / 32];
#pragma unroll
    for (int o = 16; o > 0; o >>= 1) s += __shfl_down_sync(0xffffffffu, s, o);
    if ((tid & 31) == 0) warpsum[tid >> 5] = s;
    __syncthreads();
    if (tid == 0) {
        float tot = 0.f;
#pragma unroll
        for (int w = 0; w < THREADS / 32; w++) tot += warpsum[w];
        g_partials[blockIdx.x] = tot;
    }
}

__global__ void __launch_bounds__(NBLOCKS)
finalize_kernel(float* __restrict__ out) {
    __shared__ float sh[NBLOCKS];
    const int tid = threadIdx.x;
    sh[tid] = g_partials[tid];
    __syncthreads();
#pragma unroll
    for (int s = NBLOCKS / 2; s > 0; s >>= 1) {
        if (tid < s) sh[tid] += sh[tid + s];
        __syncthreads();
    }
    if (tid == 0) {
        out[0] = sh[0] * (1.0f / (float)(KNN * BATCH * NPTS));
    }
}

extern "C" void kernel_launch(void* const* d_in, const int* in_sizes, int n_in,
                              void* d_out, int out_size) {
    const float* src  = (const float*)d_in[0];   // pc_source [B, N, 3]
    const float* tgt  = (const float*)d_in[1];   // pc_target [B, M, 3]
    const float* flow = (const float*)d_in[2];   // pred_flow [B, N, 3]
    float* out = (float*)d_out;

    chamfer_knn_kernel<<<NBLOCKS, THREADS>>>(src, tgt, flow);
    finalize_kernel<<<1, NBLOCKS>>>(out);
}

// round 8
// speedup vs baseline: 1.3695x; 1.0975x over previous
#include <cuda_runtime.h>
#include <float.h>
#include <math.h>

#define BATCH 2
#define NPTS 8192
#define KNN 16
#define TILE 2048                       // 2048 * 16B = 32 KB static smem
#define THREADS 128
#define NBLOCKS (2 * BATCH * NPTS / THREADS)   // 256
#define NQ_TOTAL (2 * BATCH * NPTS)            // 32768
#define CAP 1024                        // candidate capacity per query
#define SUB 512                         // threshold-pass subset size

__device__ float g_partials[NBLOCKS];
__device__ float g_scratch[(size_t)CAP * NQ_TOTAL];   // 134 MB static scratch

// branch-free candidate emit with a SHORT loop-carried chain:
//   setp (pred) -> selp (pred-as-DATA, 4 cyc) -> unconditional add (4 cyc chain)
//   store stays predicated (@p) but is OFF the carried chain.
// Old version used "@p add.u64" (pred-as-guard, 13 cyc, on-chain) -> 17 cyc/point serial.
__device__ __forceinline__ float* cond_store(float* wp, float sc, float tau) {
    asm volatile(
        "{\n\t"
        ".reg .pred p;\n\t"
        ".reg .u64 inc;\n\t"
        "setp.le.f32 p, %1, %2;\n\t"
        "selp.u64 inc, %3, 0, p;\n\t"
        "@p st.global.f32 [%0], %1;\n\t"
        "add.u64 %0, %0, inc;\n\t"
        "}"
        : "+l"(wp)
        : "f"(sc), "f"(tau), "n"((unsigned long long)(NQ_TOTAL * sizeof(float)))
        : "memory");
    return wp;
}

// unconditional sorted-descending top-K insert (pure FMNMX, straight-line)
__device__ __forceinline__ void bubble_insert(float* best, float sc) {
    best[0] = fminf(best[0], sc);   // replace current worst iff sc is smaller
#pragma unroll
    for (int i = 0; i < KNN - 1; i++) {
        const float a = best[i], c = best[i + 1];
        best[i]     = fmaxf(a, c);
        best[i + 1] = fminf(a, c);
    }
}

__global__ void __launch_bounds__(THREADS)
chamfer_knn_kernel(const float* __restrict__ src,
                   const float* __restrict__ tgt,
                   const float* __restrict__ flow) {
    __shared__ float4 spts[TILE];

    const int tid = threadIdx.x;
    const int gq  = blockIdx.x * THREADS + tid;       // global query slot
    const int blocks_per_set = NPTS / THREADS;        // 64
    const int set = blockIdx.x / blocks_per_set;      // (batch, direction)
    const int b   = set >> 1;
    const int dir = set & 1;                          // 0: pred->target, 1: target->pred
    const int qi  = (blockIdx.x % blocks_per_set) * THREADS + tid;

    const float* __restrict__ srcb = src  + (size_t)b * NPTS * 3;
    const float* __restrict__ tgtb = tgt  + (size_t)b * NPTS * 3;
    const float* __restrict__ flob = flow + (size_t)b * NPTS * 3;

    float qx, qy, qz;
    if (dir == 0) {
        qx = srcb[qi * 3 + 0] + flob[qi * 3 + 0];
        qy = srcb[qi * 3 + 1] + flob[qi * 3 + 1];
        qz = srcb[qi * 3 + 2] + flob[qi * 3 + 2];
    } else {
        qx = tgtb[qi * 3 + 0];
        qy = tgtb[qi * 3 + 1];
        qz = tgtb[qi * 3 + 2];
    }
    const float q2 = qx * qx + qy * qy + qz * qz;

    float best[KNN];
#pragma unroll
    for (int i = 0; i < KNN; i++) best[i] = FLT_MAX;

    float tau = FLT_MAX;
    float* const wbase  = g_scratch + gq;
    float*       wp     = wbase;
    float* const wguard = wbase + (size_t)(CAP - 8) * NQ_TOTAL;

    for (int t0 = 0; t0 < NPTS; t0 += TILE) {
        // stage ref tile as (x, y, z, |r|^2/2)
        for (int p = tid; p < TILE; p += THREADS) {
            const int g = t0 + p;
            float x, y, z;
            if (dir == 0) {
                x = tgtb[g * 3 + 0];
                y = tgtb[g * 3 + 1];
                z = tgtb[g * 3 + 2];
            } else {
                x = srcb[g * 3 + 0] + flob[g * 3 + 0];
                y = srcb[g * 3 + 1] + flob[g * 3 + 1];
                z = srcb[g * 3 + 2] + flob[g * 3 + 2];
            }
            const float w = 0.5f * (x * x + (y * y + z * z));
            spts[p] = make_float4(x, y, z, w);
        }
        __syncthreads();

        if (t0 == 0) {
            // threshold pass: exact top-16 over the first SUB points, unconditional
#pragma unroll 4
            for (int j = 0; j < SUB; j++) {
                const float4 r = spts[j];
                float sc = fmaf(-qx, r.x, r.w);
                sc = fmaf(-qy, r.y, sc);
                sc = fmaf(-qz, r.z, sc);
                bubble_insert(best, sc);
            }
            tau = best[0];   // upper bound on true 16th-smallest score
        }

        // streaming collect: branch-free predicated stores, short IADD carry chain
        for (int j0 = 0; j0 < TILE; j0 += 8) {
            tau = (wp >= wguard) ? -FLT_MAX : tau;   // SEL, never fires statistically
#pragma unroll
            for (int jj = 0; jj < 8; jj++) {
                const float4 r = spts[j0 + jj];
                float sc = fmaf(-qx, r.x, r.w);
                sc = fmaf(-qy, r.y, sc);
                sc = fmaf(-qz, r.z, sc);
                wp = cond_store(wp, sc, tau);
            }
        }
        __syncthreads();
    }

    // final exact selection over collected candidates (superset of true top-16)
    const int cnt  = (int)((wp - wbase) / NQ_TOTAL);
    const int mcnt = __reduce_max_sync(0xffffffffu, cnt);
#pragma unroll
    for (int i = 0; i < KNN; i++) best[i] = FLT_MAX;   // reinit: avoid double count

    for (int i = 0; i < mcnt; i++) {
        float v = wbase[(size_t)i * NQ_TOTAL];          // coalesced LDG
        v = (i < cnt) ? v : FLT_MAX;                    // SEL, branch-free
        bubble_insert(best, v);
    }

    // sum of the 16 euclidean distances: d = sqrt(2*score + |q|^2)
    float s = 0.f;
#pragma unroll
    for (int i = 0; i < KNN; i++) {
        const float d2 = fmaf(2.f, best[i], q2);
        s += sqrtf(fmaxf(d2, 0.f));
    }

    // deterministic block reduction
    __shared__ float warpsum[THREADS / 32];
#pragma unroll
    for (int o = 16; o > 0; o >>= 1) s += __shfl_down_sync(0xffffffffu, s, o);
    if ((tid & 31) == 0) warpsum[tid >> 5] = s;
    __syncthreads();
    if (tid == 0) {
        float tot = 0.f;
#pragma unroll
        for (int w = 0; w < THREADS / 32; w++) tot += warpsum[w];
        g_partials[blockIdx.x] = tot;
    }
}

__global__ void __launch_bounds__(NBLOCKS)
finalize_kernel(float* __restrict__ out) {
    __shared__ float sh[NBLOCKS];
    const int tid = threadIdx.x;
    sh[tid] = g_partials[tid];
    __syncthreads();
#pragma unroll
    for (int s = NBLOCKS / 2; s > 0; s >>= 1) {
        if (tid < s) sh[tid] += sh[tid + s];
        __syncthreads();
    }
    if (tid == 0) {
        out[0] = sh[0] * (1.0f / (float)(KNN * BATCH * NPTS));
    }
}

extern "C" void kernel_launch(void* const* d_in, const int* in_sizes, int n_in,
                              void* d_out, int out_size) {
    const float* src  = (const float*)d_in[0];   // pc_source [B, N, 3]
    const float* tgt  = (const float*)d_in[1];   // pc_target [B, M, 3]
    const float* flow = (const float*)d_in[2];   // pred_flow [B, N, 3]
    float* out = (float*)d_out;

    chamfer_knn_kernel<<<NBLOCKS, THREADS>>>(src, tgt, flow);
    finalize_kernel<<<1, NBLOCKS>>>(out);
}

// round 9
// speedup vs baseline: 1.3832x; 1.0100x over previous
#include <cuda_runtime.h>
#include <float.h>
#include <math.h>

#define BATCH 2
#define NPTS 8192
#define KNN 16
#define TILE 2048                       // 2048 * 16B = 32 KB static smem
#define THREADS 128
#define NBLOCKS (2 * BATCH * NPTS / THREADS)   // 256
#define NQ_TOTAL (2 * BATCH * NPTS)            // 32768
#define CAP 1024                        // candidate capacity per query
#define SUB 512                         // threshold-pass subset size
#define UNR 8

__device__ float g_partials[NBLOCKS];
__device__ float g_scratch[(size_t)CAP * NQ_TOTAL];   // 134 MB static scratch

// branch-free candidate emit; carried chain is selp(4)+add(4) only.
__device__ __forceinline__ float* cond_store(float* wp, float sc, float tau) {
    asm volatile(
        "{\n\t"
        ".reg .pred p;\n\t"
        ".reg .u64 inc;\n\t"
        "setp.le.f32 p, %1, %2;\n\t"
        "selp.u64 inc, %3, 0, p;\n\t"
        "@p st.global.f32 [%0], %1;\n\t"
        "add.u64 %0, %0, inc;\n\t"
        "}"
        : "+l"(wp)
        : "f"(sc), "f"(tau), "n"((unsigned long long)(NQ_TOTAL * sizeof(float)))
        : "memory");
    return wp;
}

// unconditional sorted-descending top-K insert (pure FMNMX, straight-line)
__device__ __forceinline__ void bubble_insert(float* best, float sc) {
    best[0] = fminf(best[0], sc);
#pragma unroll
    for (int i = 0; i < KNN - 1; i++) {
        const float a = best[i], c = best[i + 1];
        best[i]     = fmaxf(a, c);
        best[i + 1] = fminf(a, c);
    }
}

__global__ void __launch_bounds__(THREADS)
chamfer_knn_kernel(const float* __restrict__ src,
                   const float* __restrict__ tgt,
                   const float* __restrict__ flow) {
    __shared__ float4 spts[TILE];

    const int tid = threadIdx.x;
    const int gq  = blockIdx.x * THREADS + tid;       // global query slot
    const int blocks_per_set = NPTS / THREADS;        // 64
    const int set = blockIdx.x / blocks_per_set;      // (batch, direction)
    const int b   = set >> 1;
    const int dir = set & 1;                          // 0: pred->target, 1: target->pred
    const int qi  = (blockIdx.x % blocks_per_set) * THREADS + tid;

    const float* __restrict__ srcb = src  + (size_t)b * NPTS * 3;
    const float* __restrict__ tgtb = tgt  + (size_t)b * NPTS * 3;
    const float* __restrict__ flob = flow + (size_t)b * NPTS * 3;

    float qx, qy, qz;
    if (dir == 0) {
        qx = srcb[qi * 3 + 0] + flob[qi * 3 + 0];
        qy = srcb[qi * 3 + 1] + flob[qi * 3 + 1];
        qz = srcb[qi * 3 + 2] + flob[qi * 3 + 2];
    } else {
        qx = tgtb[qi * 3 + 0];
        qy = tgtb[qi * 3 + 1];
        qz = tgtb[qi * 3 + 2];
    }
    const float q2 = qx * qx + qy * qy + qz * qz;

    float best[KNN];
#pragma unroll
    for (int i = 0; i < KNN; i++) best[i] = FLT_MAX;

    float tau = FLT_MAX;
    float* const wbase  = g_scratch + gq;
    float*       wp     = wbase;
    float* const wguard = wbase + (size_t)(CAP - UNR) * NQ_TOTAL;

    for (int t0 = 0; t0 < NPTS; t0 += TILE) {
        // stage ref tile as (x, y, z, |r|^2/2)
        for (int p = tid; p < TILE; p += THREADS) {
            const int g = t0 + p;
            float x, y, z;
            if (dir == 0) {
                x = tgtb[g * 3 + 0];
                y = tgtb[g * 3 + 1];
                z = tgtb[g * 3 + 2];
            } else {
                x = srcb[g * 3 + 0] + flob[g * 3 + 0];
                y = srcb[g * 3 + 1] + flob[g * 3 + 1];
                z = srcb[g * 3 + 2] + flob[g * 3 + 2];
            }
            const float w = 0.5f * (x * x + (y * y + z * z));
            spts[p] = make_float4(x, y, z, w);
        }
        __syncthreads();

        if (t0 == 0) {
            // threshold pass: batch-load/score UNR points, then bubble them.
            for (int j0 = 0; j0 < SUB; j0 += UNR) {
                float sc[UNR];
#pragma unroll
                for (int jj = 0; jj < UNR; jj++) {
                    const float4 r = spts[j0 + jj];     // batched LDS.128 (MLP=UNR)
                    float t = fmaf(-qx, r.x, r.w);
                    t = fmaf(-qy, r.y, t);
                    sc[jj] = fmaf(-qz, r.z, t);
                }
#pragma unroll
                for (int jj = 0; jj < UNR; jj++) bubble_insert(best, sc[jj]);
            }
            tau = best[0];   // upper bound on true 16th-smallest score
        }

        // streaming collect: phase 1 batches loads+scores (no asm in the way),
        // phase 2 runs the branch-free predicated stores.
        for (int j0 = 0; j0 < TILE; j0 += UNR) {
            tau = (wp >= wguard) ? -FLT_MAX : tau;   // SEL, never fires statistically
            float sc[UNR];
#pragma unroll
            for (int jj = 0; jj < UNR; jj++) {
                const float4 r = spts[j0 + jj];     // batched LDS.128 (MLP=UNR)
                float t = fmaf(-qx, r.x, r.w);
                t = fmaf(-qy, r.y, t);
                sc[jj] = fmaf(-qz, r.z, t);
            }
#pragma unroll
            for (int jj = 0; jj < UNR; jj++) wp = cond_store(wp, sc[jj], tau);
        }
        __syncthreads();
    }

    // final exact selection over collected candidates (superset of true top-16)
    const int cnt  = (int)((wp - wbase) / NQ_TOTAL);
    const int mcnt = __reduce_max_sync(0xffffffffu, cnt);
#pragma unroll
    for (int i = 0; i < KNN; i++) best[i] = FLT_MAX;   // reinit: avoid double count

    for (int i = 0; i < mcnt; i += 4) {
        float v[4];
#pragma unroll
        for (int u = 0; u < 4; u++) {
            const int idx = i + u;
            float t = (idx < mcnt) ? wbase[(size_t)idx * NQ_TOTAL] : FLT_MAX;  // batched LDG
            v[u] = (idx < cnt) ? t : FLT_MAX;
        }
#pragma unroll
        for (int u = 0; u < 4; u++) bubble_insert(best, v[u]);
    }

    // sum of the 16 euclidean distances: d = sqrt(2*score + |q|^2)
    float s = 0.f;
#pragma unroll
    for (int i = 0; i < KNN; i++) {
        const float d2 = fmaf(2.f, best[i], q2);
        s += sqrtf(fmaxf(d2, 0.f));
    }

    // deterministic block reduction
    __shared__ float warpsum[THREADS / 32];
#pragma unroll
    for (int o = 16; o > 0; o >>= 1) s += __shfl_down_sync(0xffffffffu, s, o);
    if ((tid & 31) == 0) warpsum[tid >> 5] = s;
    __syncthreads();
    if (tid == 0) {
        float tot = 0.f;
#pragma unroll
        for (int w = 0; w < THREADS / 32; w++) tot += warpsum[w];
        g_partials[blockIdx.x] = tot;
    }
}

__global__ void __launch_bounds__(NBLOCKS)
finalize_kernel(float* __restrict__ out) {
    __shared__ float sh[NBLOCKS];
    const int tid = threadIdx.x;
    sh[tid] = g_partials[tid];
    __syncthreads();
#pragma unroll
    for (int s = NBLOCKS / 2; s > 0; s >>= 1) {
        if (tid < s) sh[tid] += sh[tid + s];
        __syncthreads();
    }
    if (tid == 0) {
        out[0] = sh[0] * (1.0f / (float)(KNN * BATCH * NPTS));
    }
}

extern "C" void kernel_launch(void* const* d_in, const int* in_sizes, int n_in,
                              void* d_out, int out_size) {
    const float* src  = (const float*)d_in[0];   // pc_source [B, N, 3]
    const float* tgt  = (const float*)d_in[1];   // pc_target [B, M, 3]
    const float* flow = (const float*)d_in[2];   // pred_flow [B, N, 3]
    float* out = (float*)d_out;

    chamfer_knn_kernel<<<NBLOCKS, THREADS>>>(src, tgt, flow);
    finalize_kernel<<<1, NBLOCKS>>>(out);
}